// round 3
// baseline (speedup 1.0000x reference)
#include <cuda_runtime.h>

static constexpr int HID  = 128;
static constexpr int MAXN = 50000;

// Scratch (device globals: no allocation allowed in kernel_launch)
__device__ float g_deg_inv[MAXN];
__device__ float g_agg[(long long)MAXN * HID];
__device__ float g_h1 [(long long)MAXN * HID];
__device__ float g_h2 [(long long)MAXN * HID];

__global__ void zero_f4(float4* __restrict__ p, int n4) {
    int i = blockIdx.x * blockDim.x + threadIdx.x;
    if (i < n4) p[i] = make_float4(0.f, 0.f, 0.f, 0.f);
}

__global__ void deg_count(const int* __restrict__ dst, int E) {
    int e = blockIdx.x * blockDim.x + threadIdx.x;
    if (e < E) atomicAdd(&g_deg_inv[dst[e]], 1.0f);
}

__global__ void deg_invert(int N) {
    int i = blockIdx.x * blockDim.x + threadIdx.x;
    if (i < N) g_deg_inv[i] = 1.0f / fmaxf(g_deg_inv[i], 1.0f);
}

// One warp per edge: 32 lanes each move one float4 of the 128-float row.
// Vector RED (sm_90+): one 128B-class atomic per lane instead of 4 scalar REDs.
__global__ void scatter_add(const float* __restrict__ X,
                            const int* __restrict__ src,
                            const int* __restrict__ dst, int E) {
    int idx = blockIdx.x * blockDim.x + threadIdx.x;
    int e = idx >> 5;
    if (e >= E) return;
    int c = idx & 31;
    int s = src[e];
    int d = dst[e];
    float4 v = ((const float4*)(X + (long long)s * HID))[c];
    float* p = g_agg + (long long)d * HID + c * 4;
    asm volatile("red.global.add.v4.f32 [%0], {%1, %2, %3, %4};"
                 :: "l"(p), "f"(v.x), "f"(v.y), "f"(v.z), "f"(v.w)
                 : "memory");
}

// Fused SAGE layer: Y[i,:] = act( (agg[i]/deg[i]) @ Wl + X[i] @ Wr + b )
// Treated as [N,256] @ [256,OUTC] with concatenated input/weight.
// Block: 256 threads, 64-node tile. Full weight (256 x OUTC) + input tile in smem.
template<int OUTC, bool RELU>
__global__ __launch_bounds__(256, 1)
void sage_layer(const float* __restrict__ X,
                const float* __restrict__ Wl, const float* __restrict__ Wr,
                const float* __restrict__ b, float* __restrict__ Y, int N) {
    extern __shared__ float sm[];
    float* sIn = sm;                    // [64][256]
    float* sW  = sm + 64 * 256;         // [256][OUTC]  rows 0..127 = Wl, 128..255 = Wr
    float* sB  = sW + 256 * OUTC;       // [OUTC]

    const int t = threadIdx.x;
    const int node0 = blockIdx.x * 64;

    // Stage weights
    const int WQ = (HID * OUTC) / 4;
    for (int i = t; i < WQ; i += 256) {
        ((float4*)sW)[i]                 = ((const float4*)Wl)[i];
        ((float4*)(sW + HID * OUTC))[i]  = ((const float4*)Wr)[i];
    }
    if (t < OUTC) sB[t] = b[t];

    // Stage input tile: [64 nodes][agg/deg (128) | x (128)]
    for (int i = t; i < 64 * 32; i += 256) {
        int r = i >> 5, c = i & 31;
        int node = node0 + r;
        float4 va = make_float4(0.f, 0.f, 0.f, 0.f);
        float4 vx = va;
        if (node < N) {
            float inv = g_deg_inv[node];
            va = ((const float4*)(g_agg + (long long)node * HID))[c];
            va.x *= inv; va.y *= inv; va.z *= inv; va.w *= inv;
            vx = ((const float4*)(X + (long long)node * HID))[c];
        }
        ((float4*)(sIn + r * 256))[c]       = va;
        ((float4*)(sIn + r * 256 + HID))[c] = vx;
    }
    __syncthreads();

    constexpr int TN = OUTC / 32;   // 4 (OUTC=128) or 2 (OUTC=64)
    const int tx = t & 31;          // column group
    const int ty = t >> 5;          // node group (8 nodes each)

    float acc[8][TN];
#pragma unroll
    for (int m = 0; m < 8; m++)
#pragma unroll
        for (int j = 0; j < TN; j++) acc[m][j] = 0.f;

    const float* inBase = sIn + (ty * 8) * 256;
    const float* wBase  = sW + tx * TN;

    for (int k = 0; k < 256; k += 4) {
        float w[4][TN];
#pragma unroll
        for (int kk = 0; kk < 4; kk++) {
            if constexpr (TN == 4) {
                float4 w4 = *(const float4*)(wBase + (k + kk) * OUTC);
                w[kk][0] = w4.x; w[kk][1] = w4.y; w[kk][2] = w4.z; w[kk][3] = w4.w;
            } else {
                float2 w2 = *(const float2*)(wBase + (k + kk) * OUTC);
                w[kk][0] = w2.x; w[kk][1] = w2.y;
            }
        }
#pragma unroll
        for (int m = 0; m < 8; m++) {
            float4 a = *(const float4*)(inBase + m * 256 + k);
            float av[4] = {a.x, a.y, a.z, a.w};
#pragma unroll
            for (int kk = 0; kk < 4; kk++)
#pragma unroll
                for (int j = 0; j < TN; j++)
                    acc[m][j] = fmaf(av[kk], w[kk][j], acc[m][j]);
        }
    }

#pragma unroll
    for (int m = 0; m < 8; m++) {
        int node = node0 + ty * 8 + m;
        if (node >= N) continue;
        if constexpr (TN == 4) {
            float4 o;
            o.x = acc[m][0] + sB[tx * 4 + 0];
            o.y = acc[m][1] + sB[tx * 4 + 1];
            o.z = acc[m][2] + sB[tx * 4 + 2];
            o.w = acc[m][3] + sB[tx * 4 + 3];
            if (RELU) {
                o.x = fmaxf(o.x, 0.f); o.y = fmaxf(o.y, 0.f);
                o.z = fmaxf(o.z, 0.f); o.w = fmaxf(o.w, 0.f);
            }
            *(float4*)(Y + (long long)node * OUTC + tx * 4) = o;
        } else {
            float2 o;
            o.x = acc[m][0] + sB[tx * 2 + 0];
            o.y = acc[m][1] + sB[tx * 2 + 1];
            if (RELU) { o.x = fmaxf(o.x, 0.f); o.y = fmaxf(o.y, 0.f); }
            *(float2*)(Y + (long long)node * OUTC + tx * 2) = o;
        }
    }
}

static void run_layer_128(const float* X, const int* src, const int* dst, int E,
                          const float* Wl, const float* Wr, const float* b,
                          float* Y, int N, float* p_agg) {
    int n4 = N * HID / 4;
    zero_f4<<<(n4 + 255) / 256, 256>>>((float4*)p_agg, n4);
    int sthreads = E * 32;
    scatter_add<<<(sthreads + 255) / 256, 256>>>(X, src, dst, E);
    size_t smem = (size_t)(64 * 256 + 256 * 128 + 128) * sizeof(float);
    sage_layer<128, true><<<(N + 63) / 64, 256, smem>>>(X, Wl, Wr, b, Y, N);
}

static void run_layer_64(const float* X, const int* src, const int* dst, int E,
                         const float* Wl, const float* Wr, const float* b,
                         float* Y, int N, float* p_agg) {
    int n4 = N * HID / 4;
    zero_f4<<<(n4 + 255) / 256, 256>>>((float4*)p_agg, n4);
    int sthreads = E * 32;
    scatter_add<<<(sthreads + 255) / 256, 256>>>(X, src, dst, E);
    size_t smem = (size_t)(64 * 256 + 256 * 64 + 64) * sizeof(float);
    sage_layer<64, false><<<(N + 63) / 64, 256, smem>>>(X, Wl, Wr, b, Y, N);
}

extern "C" void kernel_launch(void* const* d_in, const int* in_sizes, int n_in,
                              void* d_out, int out_size) {
    const float* x   = (const float*)d_in[0];
    const int*   ei  = (const int*)  d_in[1];
    const float* W1l = (const float*)d_in[2];
    const float* W1r = (const float*)d_in[3];
    const float* b1  = (const float*)d_in[4];
    const float* W2l = (const float*)d_in[5];
    const float* W2r = (const float*)d_in[6];
    const float* b2  = (const float*)d_in[7];
    const float* W3l = (const float*)d_in[8];
    const float* W3r = (const float*)d_in[9];
    const float* b3  = (const float*)d_in[10];
    float* out = (float*)d_out;

    const int N = in_sizes[0] / HID;   // 50000
    const int E = in_sizes[1] / 2;     // 500000
    const int* src = ei;
    const int* dst = ei + E;

    float *p_agg, *p_h1, *p_h2, *p_deg;
    cudaGetSymbolAddress((void**)&p_agg, g_agg);
    cudaGetSymbolAddress((void**)&p_h1,  g_h1);
    cudaGetSymbolAddress((void**)&p_h2,  g_h2);
    cudaGetSymbolAddress((void**)&p_deg, g_deg_inv);

    cudaFuncSetAttribute(sage_layer<128, true>,
                         cudaFuncAttributeMaxDynamicSharedMemorySize,
                         (64 * 256 + 256 * 128 + 128) * 4);
    cudaFuncSetAttribute(sage_layer<64, false>,
                         cudaFuncAttributeMaxDynamicSharedMemorySize,
                         (64 * 256 + 256 * 64 + 64) * 4);

    // Degrees (same edge set for all layers): count then invert in place.
    {
        int n4 = N / 4;  // 50000 % 4 == 0
        zero_f4<<<(n4 + 255) / 256, 256>>>((float4*)p_deg, n4);
        deg_count<<<(E + 255) / 256, 256>>>(dst, E);
        deg_invert<<<(N + 255) / 256, 256>>>(N);
    }

    run_layer_128(x,    src, dst, E, W1l, W1r, b1, p_h1, N, p_agg);
    run_layer_128(p_h1, src, dst, E, W2l, W2r, b2, p_h2, N, p_agg);
    run_layer_64 (p_h2, src, dst, E, W3l, W3r, b3, out,  N, p_agg);
}

// round 4
// speedup vs baseline: 1.1526x; 1.1526x over previous
#include <cuda_runtime.h>

static constexpr int HID  = 128;
static constexpr int MAXN = 50000;
static constexpr int MAXE = 500000;

// Scratch (device globals: no allocation allowed in kernel_launch)
__device__ int   g_cnt[MAXN];        // per-node in-degree (histogram)
__device__ int   g_cur[MAXN];        // fill cursors
__device__ int   g_row[MAXN + 1];    // CSR row pointers
__device__ int   g_eidx[MAXE];       // CSR column indices (src node per in-edge)
__device__ float g_agg[(long long)MAXN * HID];
__device__ float g_h1 [(long long)MAXN * HID];
__device__ float g_h2 [(long long)MAXN * HID];

// ---------------- CSR construction (replaces all float atomics) ----------------

__global__ void zero_ints(int* __restrict__ a, int* __restrict__ b, int n) {
    int i = blockIdx.x * blockDim.x + threadIdx.x;
    if (i < n) { a[i] = 0; b[i] = 0; }
}

__global__ void hist_kernel(const int* __restrict__ dst, int E) {
    int e = blockIdx.x * blockDim.x + threadIdx.x;
    if (e < E) atomicAdd(&g_cnt[dst[e]], 1);
}

// Single-block exclusive scan of g_cnt[0..N) -> g_row[0..N], g_row[N] = E.
__global__ void scan_kernel(int N, int E) {
    __shared__ int part[1024];
    const int t = threadIdx.x;
    const int chunk = (N + 1023) / 1024;
    const int lo = t * chunk;
    const int hi = min(lo + chunk, N);

    int s = 0;
    for (int i = lo; i < hi; i++) s += g_cnt[i];
    part[t] = s;
    __syncthreads();
    for (int off = 1; off < 1024; off <<= 1) {
        int v = (t >= off) ? part[t - off] : 0;
        __syncthreads();
        part[t] += v;
        __syncthreads();
    }
    int excl = (t == 0) ? 0 : part[t - 1];
    for (int i = lo; i < hi; i++) {
        int c = g_cnt[i];
        g_row[i] = excl;
        excl += c;
    }
    if (t == 1023) g_row[N] = E;
}

__global__ void fill_kernel(const int* __restrict__ src,
                            const int* __restrict__ dst, int E) {
    int e = blockIdx.x * blockDim.x + threadIdx.x;
    if (e < E) {
        int d = dst[e];
        int pos = g_row[d] + atomicAdd(&g_cur[d], 1);
        g_eidx[pos] = src[e];
    }
}

// ---------------- Mean aggregation: warp-per-node CSR gather ----------------
// Lane c accumulates float4 column c of each neighbor row. Pure coalesced L2
// reads, no atomics, mean folded in. 2-way unrolled accumulators for MLP.
__global__ __launch_bounds__(256)
void csr_aggregate(const float* __restrict__ X, float* __restrict__ AGG, int N) {
    int w = (blockIdx.x * blockDim.x + threadIdx.x) >> 5;
    if (w >= N) return;
    const int lane = threadIdx.x & 31;
    const int s0 = g_row[w];
    const int s1 = g_row[w + 1];

    float4 a0 = make_float4(0.f, 0.f, 0.f, 0.f);
    float4 a1 = a0;
    int i = s0;
    for (; i + 1 < s1; i += 2) {
        int n0 = g_eidx[i];
        int n1 = g_eidx[i + 1];
        float4 v0 = ((const float4*)(X + (long long)n0 * HID))[lane];
        float4 v1 = ((const float4*)(X + (long long)n1 * HID))[lane];
        a0.x += v0.x; a0.y += v0.y; a0.z += v0.z; a0.w += v0.w;
        a1.x += v1.x; a1.y += v1.y; a1.z += v1.z; a1.w += v1.w;
    }
    if (i < s1) {
        int n0 = g_eidx[i];
        float4 v0 = ((const float4*)(X + (long long)n0 * HID))[lane];
        a0.x += v0.x; a0.y += v0.y; a0.z += v0.z; a0.w += v0.w;
    }
    float inv = 1.0f / (float)max(s1 - s0, 1);
    float4 o;
    o.x = (a0.x + a1.x) * inv;
    o.y = (a0.y + a1.y) * inv;
    o.z = (a0.z + a1.z) * inv;
    o.w = (a0.w + a1.w) * inv;
    ((float4*)(AGG + (long long)w * HID))[lane] = o;
}

// ---------------- Fused SAGE layer GEMM ----------------
// Y[i,:] = act( agg[i] @ Wl + X[i] @ Wr + b ), treated as [N,256]@[256,OUTC].
template<int OUTC, bool RELU>
__global__ __launch_bounds__(256, 1)
void sage_layer(const float* __restrict__ X, const float* __restrict__ AGG,
                const float* __restrict__ Wl, const float* __restrict__ Wr,
                const float* __restrict__ b, float* __restrict__ Y, int N) {
    extern __shared__ float sm[];
    float* sIn = sm;                    // [64][256]
    float* sW  = sm + 64 * 256;         // [256][OUTC]
    float* sB  = sW + 256 * OUTC;       // [OUTC]

    const int t = threadIdx.x;
    const int node0 = blockIdx.x * 64;

    const int WQ = (HID * OUTC) / 4;
    for (int i = t; i < WQ; i += 256) {
        ((float4*)sW)[i]                = ((const float4*)Wl)[i];
        ((float4*)(sW + HID * OUTC))[i] = ((const float4*)Wr)[i];
    }
    if (t < OUTC) sB[t] = b[t];

    for (int i = t; i < 64 * 32; i += 256) {
        int r = i >> 5, c = i & 31;
        int node = node0 + r;
        float4 va = make_float4(0.f, 0.f, 0.f, 0.f);
        float4 vx = va;
        if (node < N) {
            va = ((const float4*)(AGG + (long long)node * HID))[c];
            vx = ((const float4*)(X   + (long long)node * HID))[c];
        }
        ((float4*)(sIn + r * 256))[c]       = va;
        ((float4*)(sIn + r * 256 + HID))[c] = vx;
    }
    __syncthreads();

    constexpr int TN = OUTC / 32;   // 4 (OUTC=128) or 2 (OUTC=64)
    const int tx = t & 31;
    const int ty = t >> 5;

    float acc[8][TN];
#pragma unroll
    for (int m = 0; m < 8; m++)
#pragma unroll
        for (int j = 0; j < TN; j++) acc[m][j] = 0.f;

    const float* inBase = sIn + (ty * 8) * 256;
    const float* wBase  = sW + tx * TN;

    for (int k = 0; k < 256; k += 4) {
        float w[4][TN];
#pragma unroll
        for (int kk = 0; kk < 4; kk++) {
            if constexpr (TN == 4) {
                float4 w4 = *(const float4*)(wBase + (k + kk) * OUTC);
                w[kk][0] = w4.x; w[kk][1] = w4.y; w[kk][2] = w4.z; w[kk][3] = w4.w;
            } else {
                float2 w2 = *(const float2*)(wBase + (k + kk) * OUTC);
                w[kk][0] = w2.x; w[kk][1] = w2.y;
            }
        }
#pragma unroll
        for (int m = 0; m < 8; m++) {
            float4 a = *(const float4*)(inBase + m * 256 + k);
            float av[4] = {a.x, a.y, a.z, a.w};
#pragma unroll
            for (int kk = 0; kk < 4; kk++)
#pragma unroll
                for (int j = 0; j < TN; j++)
                    acc[m][j] = fmaf(av[kk], w[kk][j], acc[m][j]);
        }
    }

#pragma unroll
    for (int m = 0; m < 8; m++) {
        int node = node0 + ty * 8 + m;
        if (node >= N) continue;
        if constexpr (TN == 4) {
            float4 o;
            o.x = acc[m][0] + sB[tx * 4 + 0];
            o.y = acc[m][1] + sB[tx * 4 + 1];
            o.z = acc[m][2] + sB[tx * 4 + 2];
            o.w = acc[m][3] + sB[tx * 4 + 3];
            if (RELU) {
                o.x = fmaxf(o.x, 0.f); o.y = fmaxf(o.y, 0.f);
                o.z = fmaxf(o.z, 0.f); o.w = fmaxf(o.w, 0.f);
            }
            *(float4*)(Y + (long long)node * OUTC + tx * 4) = o;
        } else {
            float2 o;
            o.x = acc[m][0] + sB[tx * 2 + 0];
            o.y = acc[m][1] + sB[tx * 2 + 1];
            if (RELU) { o.x = fmaxf(o.x, 0.f); o.y = fmaxf(o.y, 0.f); }
            *(float2*)(Y + (long long)node * OUTC + tx * 2) = o;
        }
    }
}

// ---------------- Driver ----------------

template<int OUTC, bool RELU>
static void run_layer(const float* X, const float* Wl, const float* Wr,
                      const float* b, float* Y, int N, float* p_agg) {
    csr_aggregate<<<(N * 32 + 255) / 256, 256>>>(X, p_agg, N);
    size_t smem = (size_t)(64 * 256 + 256 * OUTC + OUTC) * sizeof(float);
    sage_layer<OUTC, RELU><<<(N + 63) / 64, 256, smem>>>(X, p_agg, Wl, Wr, b, Y, N);
}

extern "C" void kernel_launch(void* const* d_in, const int* in_sizes, int n_in,
                              void* d_out, int out_size) {
    const float* x   = (const float*)d_in[0];
    const int*   ei  = (const int*)  d_in[1];
    const float* W1l = (const float*)d_in[2];
    const float* W1r = (const float*)d_in[3];
    const float* b1  = (const float*)d_in[4];
    const float* W2l = (const float*)d_in[5];
    const float* W2r = (const float*)d_in[6];
    const float* b2  = (const float*)d_in[7];
    const float* W3l = (const float*)d_in[8];
    const float* W3r = (const float*)d_in[9];
    const float* b3  = (const float*)d_in[10];
    float* out = (float*)d_out;

    const int N = in_sizes[0] / HID;   // 50000
    const int E = in_sizes[1] / 2;     // 500000
    const int* src = ei;
    const int* dst = ei + E;

    float *p_agg, *p_h1, *p_h2;
    int *p_cnt, *p_cur;
    cudaGetSymbolAddress((void**)&p_agg, g_agg);
    cudaGetSymbolAddress((void**)&p_h1,  g_h1);
    cudaGetSymbolAddress((void**)&p_h2,  g_h2);
    cudaGetSymbolAddress((void**)&p_cnt, g_cnt);
    cudaGetSymbolAddress((void**)&p_cur, g_cur);

    cudaFuncSetAttribute(sage_layer<128, true>,
                         cudaFuncAttributeMaxDynamicSharedMemorySize,
                         (64 * 256 + 256 * 128 + 128) * 4);
    cudaFuncSetAttribute(sage_layer<64, false>,
                         cudaFuncAttributeMaxDynamicSharedMemorySize,
                         (64 * 256 + 256 * 64 + 64) * 4);

    // CSR build (no float atomics anywhere afterwards)
    zero_ints<<<(N + 255) / 256, 256>>>(p_cnt, p_cur, N);
    hist_kernel<<<(E + 255) / 256, 256>>>(dst, E);
    scan_kernel<<<1, 1024>>>(N, E);
    fill_kernel<<<(E + 255) / 256, 256>>>(src, dst, E);

    run_layer<128, true >(x,    W1l, W1r, b1, p_h1, N, p_agg);
    run_layer<128, true >(p_h1, W2l, W2r, b2, p_h2, N, p_agg);
    run_layer<64,  false>(p_h2, W3l, W3r, b3, out,  N, p_agg);
}

// round 7
// speedup vs baseline: 1.5691x; 1.3614x over previous
#include <cuda_runtime.h>
#include <cuda_bf16.h>
#include <cstdint>
#include <cstring>

static constexpr int HID  = 128;
static constexpr int MAXN = 50000;
static constexpr int MAXE = 500000;

// Scratch (device globals: no allocation allowed in kernel_launch)
__device__ int   g_cnt[MAXN];
__device__ int   g_cur[MAXN];
__device__ int   g_row[MAXN + 1];
__device__ int   g_eidx[MAXE];
__device__ float g_agg[(long long)MAXN * HID];
__device__ float g_h1 [(long long)MAXN * HID];
__device__ float g_h2 [(long long)MAXN * HID];
__device__ __nv_bfloat16 g_whi[128 * 256];   // [OUTC][256] n-major, k: 0-127=Wl, 128-255=Wr
__device__ __nv_bfloat16 g_wlo[128 * 256];

// ======================= CSR construction =======================

__global__ void zero_ints(int* __restrict__ a, int* __restrict__ b, int n) {
    int i = blockIdx.x * blockDim.x + threadIdx.x;
    if (i < n) { a[i] = 0; b[i] = 0; }
}

__global__ void hist_kernel(const int* __restrict__ dst, int E) {
    int e = blockIdx.x * blockDim.x + threadIdx.x;
    if (e < E) atomicAdd(&g_cnt[dst[e]], 1);
}

__global__ void scan_kernel(int N, int E) {
    __shared__ int part[1024];
    const int t = threadIdx.x;
    const int chunk = (N + 1023) / 1024;
    const int lo = t * chunk;
    const int hi = min(lo + chunk, N);
    int s = 0;
    for (int i = lo; i < hi; i++) s += g_cnt[i];
    part[t] = s;
    __syncthreads();
    for (int off = 1; off < 1024; off <<= 1) {
        int v = (t >= off) ? part[t - off] : 0;
        __syncthreads();
        part[t] += v;
        __syncthreads();
    }
    int excl = (t == 0) ? 0 : part[t - 1];
    for (int i = lo; i < hi; i++) {
        int c = g_cnt[i];
        g_row[i] = excl;
        excl += c;
    }
    if (t == 1023) g_row[N] = E;
}

__global__ void fill_kernel(const int* __restrict__ src,
                            const int* __restrict__ dst, int E) {
    int e = blockIdx.x * blockDim.x + threadIdx.x;
    if (e < E) {
        int d = dst[e];
        int pos = g_row[d] + atomicAdd(&g_cur[d], 1);
        g_eidx[pos] = src[e];
    }
}

// ======================= Mean aggregation (warp-per-node gather) =======================

__global__ __launch_bounds__(256)
void csr_aggregate(const float* __restrict__ X, float* __restrict__ AGG, int N) {
    int w = (blockIdx.x * blockDim.x + threadIdx.x) >> 5;
    if (w >= N) return;
    const int lane = threadIdx.x & 31;
    const int s0 = g_row[w];
    const int s1 = g_row[w + 1];

    float4 a0 = make_float4(0.f, 0.f, 0.f, 0.f);
    float4 a1 = a0;
    int i = s0;
    for (; i + 1 < s1; i += 2) {
        int n0 = g_eidx[i];
        int n1 = g_eidx[i + 1];
        float4 v0 = ((const float4*)(X + (long long)n0 * HID))[lane];
        float4 v1 = ((const float4*)(X + (long long)n1 * HID))[lane];
        a0.x += v0.x; a0.y += v0.y; a0.z += v0.z; a0.w += v0.w;
        a1.x += v1.x; a1.y += v1.y; a1.z += v1.z; a1.w += v1.w;
    }
    if (i < s1) {
        int n0 = g_eidx[i];
        float4 v0 = ((const float4*)(X + (long long)n0 * HID))[lane];
        a0.x += v0.x; a0.y += v0.y; a0.z += v0.z; a0.w += v0.w;
    }
    float inv = 1.0f / (float)max(s1 - s0, 1);
    float4 o;
    o.x = (a0.x + a1.x) * inv;
    o.y = (a0.y + a1.y) * inv;
    o.z = (a0.z + a1.z) * inv;
    o.w = (a0.w + a1.w) * inv;
    ((float4*)(AGG + (long long)w * HID))[lane] = o;
}

// ======================= Weight prep: fp32 -> split bf16, n-major =======================

__device__ __forceinline__ void split_bf(float x, __nv_bfloat16& h, __nv_bfloat16& l) {
    h = __float2bfloat16(x);
    l = __float2bfloat16(x - __bfloat162float(h));
}

template<int OUTC>
__global__ void prep_w(const float* __restrict__ Wl, const float* __restrict__ Wr) {
    int i = blockIdx.x * blockDim.x + threadIdx.x;
    if (i >= OUTC * 256) return;
    int n = i >> 8;
    int k = i & 255;
    float v = (k < 128) ? Wl[k * OUTC + n] : Wr[(k - 128) * OUTC + n];
    __nv_bfloat16 h, l;
    split_bf(v, h, l);
    g_whi[n * 256 + k] = h;
    g_wlo[n * 256 + k] = l;
}

// ======================= bf16 mma.sync SAGE layer =======================
// Y = act([agg|x] @ [Wl;Wr] + b) with D = Ah*Bh + Ah*Bl + Al*Bh (fp32 accum).
// CTA: 64-node tile x OUTC, 256 threads (8 warps, 2M x 4N warp grid).

static constexpr int ASTR = 264;                 // padded stride (bf16 elems)
static constexpr int A_BYTES = 64 * ASTR * 2;    // 33792

__device__ __forceinline__ void ldmA(uint32_t a[4], uint32_t addr) {
    asm volatile("ldmatrix.sync.aligned.m8n8.x4.shared.b16 {%0,%1,%2,%3}, [%4];"
                 : "=r"(a[0]), "=r"(a[1]), "=r"(a[2]), "=r"(a[3]) : "r"(addr));
}

__device__ __forceinline__ void mma16816(float c[4], const uint32_t a[4], const uint32_t b[2]) {
    asm volatile(
        "mma.sync.aligned.m16n8k16.row.col.f32.bf16.bf16.f32 "
        "{%0,%1,%2,%3}, {%4,%5,%6,%7}, {%8,%9}, {%0,%1,%2,%3};"
        : "+f"(c[0]), "+f"(c[1]), "+f"(c[2]), "+f"(c[3])
        : "r"(a[0]), "r"(a[1]), "r"(a[2]), "r"(a[3]), "r"(b[0]), "r"(b[1]));
}

__device__ __forceinline__ uint32_t smem_u32(const void* p) {
    uint32_t a;
    asm("{ .reg .u64 t; cvta.to.shared.u64 t, %1; cvt.u32.u64 %0, t; }"
        : "=r"(a) : "l"(p));
    return a;
}

template<int OUTC, bool RELU>
__global__ __launch_bounds__(256, 1)
void sage_mma(const float* __restrict__ X, const float* __restrict__ AGG,
              const float* __restrict__ bias, float* __restrict__ Y, int N) {
    extern __shared__ char smem[];
    constexpr int OFF_AH = 0;
    constexpr int OFF_AL = A_BYTES;
    constexpr int OFF_BH = 2 * A_BYTES;
    constexpr int B_BYTES = OUTC * ASTR * 2;
    constexpr int OFF_BL = OFF_BH + B_BYTES;

    const int t = threadIdx.x;
    const int wid = t >> 5;
    const int lane = t & 31;
    const int node0 = blockIdx.x * 64;

    // ---- Stage A (split hi/lo into padded smem) ----
    for (int i = t; i < 64 * 64; i += 256) {
        int row = i >> 6;
        int k = (i & 63) * 4;
        int node = node0 + row;
        float4 v = make_float4(0.f, 0.f, 0.f, 0.f);
        if (node < N) {
            v = (k < 128)
                ? ((const float4*)(AGG + (long long)node * HID))[k >> 2]
                : ((const float4*)(X   + (long long)node * HID))[(k - 128) >> 2];
        }
        __nv_bfloat16 h0, h1, h2, h3, l0, l1, l2, l3;
        split_bf(v.x, h0, l0); split_bf(v.y, h1, l1);
        split_bf(v.z, h2, l2); split_bf(v.w, h3, l3);
        __nv_bfloat162 hA(h0, h1), hB(h2, h3), lA(l0, l1), lB(l2, l3);
        uint2 hp, lp;
        memcpy(&hp.x, &hA, 4); memcpy(&hp.y, &hB, 4);
        memcpy(&lp.x, &lA, 4); memcpy(&lp.y, &lB, 4);
        uint32_t off = (uint32_t)(row * (ASTR * 2) + k * 2);
        *(uint2*)(smem + OFF_AH + off) = hp;
        *(uint2*)(smem + OFF_AL + off) = lp;
    }

    // ---- Stage B from precomputed global hi/lo (n-major [OUTC][256]) ----
    for (int i = t; i < OUTC * 32; i += 256) {
        int n = i >> 5;
        int c = i & 31;                      // 16B chunk (8 bf16)
        uint32_t off = (uint32_t)(n * (ASTR * 2) + c * 16);
        *(uint4*)(smem + OFF_BH + off) = ((const uint4*)g_whi)[n * 32 + c];
        *(uint4*)(smem + OFF_BL + off) = ((const uint4*)g_wlo)[n * 32 + c];
    }
    __syncthreads();

    // ---- Warp tiling ----
    const int warp_m = wid >> 2;             // 0..1 (32 rows each)
    const int warp_n = wid & 3;              // 0..3
    constexpr int WN = OUTC / 4;             // 32 or 16
    constexpr int NB = WN / 8;               // 4 or 2

    const int tid4 = lane & 3;
    const int grp  = lane >> 2;

    float acc[2][NB][4];
#pragma unroll
    for (int m = 0; m < 2; m++)
#pragma unroll
        for (int nb = 0; nb < NB; nb++)
#pragma unroll
            for (int j = 0; j < 4; j++) acc[m][nb][j] = 0.f;

    const uint32_t sbase = smem_u32(smem);
    // ldmatrix lane address pieces
    const int arow_in = lane & 15;
    const int acol    = (lane >> 4) * 8;

#pragma unroll 1
    for (int term = 0; term < 3; term++) {
        const uint32_t Abase = sbase + ((term == 2) ? OFF_AL : OFF_AH);
        const uint32_t Bbase = sbase + ((term == 1) ? OFF_BL : OFF_BH);
        const uint32_t aAddr0 = Abase + (uint32_t)((warp_m * 32 + arow_in) * (ASTR * 2));
        const uint32_t bAddr0 = Bbase + (uint32_t)((warp_n * WN + grp) * (ASTR * 2));
#pragma unroll
        for (int k0 = 0; k0 < 256; k0 += 16) {
            uint32_t a[2][4];
#pragma unroll
            for (int m = 0; m < 2; m++)
                ldmA(a[m], aAddr0 + (uint32_t)(m * 16 * (ASTR * 2) + (k0 + acol) * 2));
            uint32_t bf[NB][2];
#pragma unroll
            for (int nb = 0; nb < NB; nb++) {
                uint32_t ba = bAddr0 + (uint32_t)(nb * 8 * (ASTR * 2) + (k0 + tid4 * 2) * 2);
                asm volatile("ld.shared.b32 %0, [%1];" : "=r"(bf[nb][0]) : "r"(ba));
                asm volatile("ld.shared.b32 %0, [%1];" : "=r"(bf[nb][1]) : "r"(ba + 16));
            }
#pragma unroll
            for (int m = 0; m < 2; m++)
#pragma unroll
                for (int nb = 0; nb < NB; nb++)
                    mma16816(acc[m][nb], a[m], bf[nb]);
        }
    }

    // ---- Epilogue: bias + activation, direct global store ----
#pragma unroll
    for (int nb = 0; nb < NB; nb++) {
        const int col0 = warp_n * WN + nb * 8 + tid4 * 2;
        const float bx = __ldg(bias + col0);
        const float by = __ldg(bias + col0 + 1);
#pragma unroll
        for (int m = 0; m < 2; m++) {
            int r0 = node0 + warp_m * 32 + m * 16 + grp;
#pragma unroll
            for (int h = 0; h < 2; h++) {
                int node = r0 + h * 8;
                if (node < N) {
                    float2 o;
                    o.x = acc[m][nb][h * 2 + 0] + bx;
                    o.y = acc[m][nb][h * 2 + 1] + by;
                    if (RELU) { o.x = fmaxf(o.x, 0.f); o.y = fmaxf(o.y, 0.f); }
                    *(float2*)(Y + (long long)node * OUTC + col0) = o;
                }
            }
        }
    }
}

// ======================= Driver =======================

template<int OUTC, bool RELU>
static void run_layer(const float* X, const float* Wl, const float* Wr,
                      const float* b, float* Y, int N, float* p_agg) {
    prep_w<OUTC><<<(OUTC * 256 + 255) / 256, 256>>>(Wl, Wr);
    csr_aggregate<<<(N * 32 + 255) / 256, 256>>>(X, p_agg, N);
    size_t smem = 2 * A_BYTES + 2 * (size_t)OUTC * ASTR * 2;
    sage_mma<OUTC, RELU><<<(N + 63) / 64, 256, smem>>>(X, p_agg, b, Y, N);
}

extern "C" void kernel_launch(void* const* d_in, const int* in_sizes, int n_in,
                              void* d_out, int out_size) {
    const float* x   = (const float*)d_in[0];
    const int*   ei  = (const int*)  d_in[1];
    const float* W1l = (const float*)d_in[2];
    const float* W1r = (const float*)d_in[3];
    const float* b1  = (const float*)d_in[4];
    const float* W2l = (const float*)d_in[5];
    const float* W2r = (const float*)d_in[6];
    const float* b2  = (const float*)d_in[7];
    const float* W3l = (const float*)d_in[8];
    const float* W3r = (const float*)d_in[9];
    const float* b3  = (const float*)d_in[10];
    float* out = (float*)d_out;

    const int N = in_sizes[0] / HID;   // 50000
    const int E = in_sizes[1] / 2;     // 500000
    const int* src = ei;
    const int* dst = ei + E;

    float *p_agg, *p_h1, *p_h2;
    int *p_cnt, *p_cur;
    cudaGetSymbolAddress((void**)&p_agg, g_agg);
    cudaGetSymbolAddress((void**)&p_h1,  g_h1);
    cudaGetSymbolAddress((void**)&p_h2,  g_h2);
    cudaGetSymbolAddress((void**)&p_cnt, g_cnt);
    cudaGetSymbolAddress((void**)&p_cur, g_cur);

    cudaFuncSetAttribute(sage_mma<128, true>,
                         cudaFuncAttributeMaxDynamicSharedMemorySize,
                         2 * A_BYTES + 2 * 128 * ASTR * 2);
    cudaFuncSetAttribute(sage_mma<64, false>,
                         cudaFuncAttributeMaxDynamicSharedMemorySize,
                         2 * A_BYTES + 2 * 64 * ASTR * 2);

    // CSR build
    zero_ints<<<(N + 255) / 256, 256>>>(p_cnt, p_cur, N);
    hist_kernel<<<(E + 255) / 256, 256>>>(dst, E);
    scan_kernel<<<1, 1024>>>(N, E);
    fill_kernel<<<(E + 255) / 256, 256>>>(src, dst, E);

    run_layer<128, true >(x,    W1l, W1r, b1, p_h1, N, p_agg);
    run_layer<128, true >(p_h1, W2l, W2r, b2, p_h2, N, p_agg);
    run_layer<64,  false>(p_h2, W3l, W3r, b3, out,  N, p_agg);
}

// round 9
// speedup vs baseline: 2.5439x; 1.6213x over previous
#include <cuda_runtime.h>
#include <cuda_bf16.h>
#include <cstdint>
#include <cstring>

static constexpr int HID  = 128;
static constexpr int MAXN = 50000;
static constexpr int MAXE = 500000;

// Scratch (device globals: no allocation allowed in kernel_launch)
__device__ int   g_cnt[MAXN];
__device__ int   g_cur[MAXN];
__device__ int   g_row[MAXN + 1];
__device__ int   g_bsum[256];
__device__ int   g_eidx[MAXE];
__device__ float g_agg[(long long)MAXN * HID];
__device__ float g_h1 [(long long)MAXN * HID];
__device__ float g_h2 [(long long)MAXN * HID];
// Split-bf16 weights, n-major [OUTC][256] (k: 0-127 = Wl, 128-255 = Wr).
// Layer offsets (elems): L1 @ 0, L2 @ 32768, L3 @ 65536.
__device__ __nv_bfloat16 g_whi[81920];
__device__ __nv_bfloat16 g_wlo[81920];

// ======================= CSR construction =======================

__global__ void zero_ints(int* __restrict__ a, int* __restrict__ b, int n) {
    int i = blockIdx.x * blockDim.x + threadIdx.x;
    if (i < n) { a[i] = 0; b[i] = 0; }
}

__global__ void hist_kernel(const int* __restrict__ dst, int E) {
    int e = blockIdx.x * blockDim.x + threadIdx.x;
    if (e < E) atomicAdd(&g_cnt[dst[e]], 1);
}

// Hierarchical scan: per-block exclusive scan + block totals.
__global__ void scan_blk(int N) {
    __shared__ int sh[256];
    const int t = threadIdx.x;
    const int i = blockIdx.x * 256 + t;
    int v = (i < N) ? g_cnt[i] : 0;
    sh[t] = v;
    __syncthreads();
    for (int off = 1; off < 256; off <<= 1) {
        int u = (t >= off) ? sh[t - off] : 0;
        __syncthreads();
        sh[t] += u;
        __syncthreads();
    }
    if (i < N) g_row[i] = sh[t] - v;          // exclusive within block
    if (t == 255) g_bsum[blockIdx.x] = sh[255];
}

__global__ void scan_bsum(int B) {
    __shared__ int sh[256];
    const int t = threadIdx.x;
    int v = (t < B) ? g_bsum[t] : 0;
    sh[t] = v;
    __syncthreads();
    for (int off = 1; off < 256; off <<= 1) {
        int u = (t >= off) ? sh[t - off] : 0;
        __syncthreads();
        sh[t] += u;
        __syncthreads();
    }
    if (t < B) g_bsum[t] = sh[t] - v;          // exclusive block offsets
}

__global__ void scan_add(int N, int E) {
    int i = blockIdx.x * 256 + threadIdx.x;
    if (i < N) g_row[i] += g_bsum[blockIdx.x];
    if (i == 0) g_row[N] = E;
}

__global__ void fill_kernel(const int* __restrict__ src,
                            const int* __restrict__ dst, int E) {
    int e = blockIdx.x * blockDim.x + threadIdx.x;
    if (e < E) {
        int d = dst[e];
        int pos = g_row[d] + atomicAdd(&g_cur[d], 1);
        g_eidx[pos] = src[e];
    }
}

// ======================= Mean aggregation (warp-per-node gather) =======================

__global__ __launch_bounds__(256)
void csr_aggregate(const float* __restrict__ X, float* __restrict__ AGG, int N) {
    int w = (blockIdx.x * blockDim.x + threadIdx.x) >> 5;
    if (w >= N) return;
    const int lane = threadIdx.x & 31;
    const int s0 = g_row[w];
    const int s1 = g_row[w + 1];

    float4 a0 = make_float4(0.f, 0.f, 0.f, 0.f);
    float4 a1 = a0;
    int i = s0;
    for (; i + 1 < s1; i += 2) {
        int n0 = g_eidx[i];
        int n1 = g_eidx[i + 1];
        float4 v0 = ((const float4*)(X + (long long)n0 * HID))[lane];
        float4 v1 = ((const float4*)(X + (long long)n1 * HID))[lane];
        a0.x += v0.x; a0.y += v0.y; a0.z += v0.z; a0.w += v0.w;
        a1.x += v1.x; a1.y += v1.y; a1.z += v1.z; a1.w += v1.w;
    }
    if (i < s1) {
        int n0 = g_eidx[i];
        float4 v0 = ((const float4*)(X + (long long)n0 * HID))[lane];
        a0.x += v0.x; a0.y += v0.y; a0.z += v0.z; a0.w += v0.w;
    }
    float inv = 1.0f / (float)max(s1 - s0, 1);
    float4 o;
    o.x = (a0.x + a1.x) * inv;
    o.y = (a0.y + a1.y) * inv;
    o.z = (a0.z + a1.z) * inv;
    o.w = (a0.w + a1.w) * inv;
    ((float4*)(AGG + (long long)w * HID))[lane] = o;
}

// ======================= Weight prep (all 3 layers, one kernel) =======================

__device__ __forceinline__ void split_bf(float x, __nv_bfloat16& h, __nv_bfloat16& l) {
    h = __float2bfloat16(x);
    l = __float2bfloat16(x - __bfloat162float(h));
}

__global__ void prep_w_all(const float* __restrict__ W1l, const float* __restrict__ W1r,
                           const float* __restrict__ W2l, const float* __restrict__ W2r,
                           const float* __restrict__ W3l, const float* __restrict__ W3r) {
    int i = blockIdx.x * blockDim.x + threadIdx.x;
    if (i >= 81920) return;
    const float *Wl, *Wr;
    int outc, base;
    if (i < 32768)      { Wl = W1l; Wr = W1r; outc = 128; base = 0; }
    else if (i < 65536) { Wl = W2l; Wr = W2r; outc = 128; base = 32768; }
    else                { Wl = W3l; Wr = W3r; outc = 64;  base = 65536; }
    int li = i - base;
    int n = li >> 8;
    int k = li & 255;
    float v = (k < 128) ? Wl[k * outc + n] : Wr[(k - 128) * outc + n];
    __nv_bfloat16 h, l;
    split_bf(v, h, l);
    g_whi[i] = h;
    g_wlo[i] = l;
}

// ======================= bf16 mma.sync SAGE layer =======================
// Y = act(agg @ Wl + x @ Wr + b), D = Ah*Bh + Ah*Bl + Al*Bh (fp32 accum).
// Two K-phases (phase 0: agg/Wl, phase 1: x/Wr); accumulators persist.
// CTA: 64-node tile x OUTC, 256 threads (2M x 4N warp grid), 2 CTAs/SM.

static constexpr int ASTR  = 136;                 // elems; 272B row stride (4-bank shift, conflict-free)
static constexpr int A_BYT = 64 * ASTR * 2;       // 17408

__device__ __forceinline__ void ldmA(uint32_t a[4], uint32_t addr) {
    asm volatile("ldmatrix.sync.aligned.m8n8.x4.shared.b16 {%0,%1,%2,%3}, [%4];"
                 : "=r"(a[0]), "=r"(a[1]), "=r"(a[2]), "=r"(a[3]) : "r"(addr));
}

__device__ __forceinline__ void mma16816(float c[4], const uint32_t a[4], const uint32_t b[2]) {
    asm volatile(
        "mma.sync.aligned.m16n8k16.row.col.f32.bf16.bf16.f32 "
        "{%0,%1,%2,%3}, {%4,%5,%6,%7}, {%8,%9}, {%0,%1,%2,%3};"
        : "+f"(c[0]), "+f"(c[1]), "+f"(c[2]), "+f"(c[3])
        : "r"(a[0]), "r"(a[1]), "r"(a[2]), "r"(a[3]), "r"(b[0]), "r"(b[1]));
}

__device__ __forceinline__ uint32_t smem_u32(const void* p) {
    uint32_t a;
    asm("{ .reg .u64 t; cvta.to.shared.u64 t, %1; cvt.u32.u64 %0, t; }"
        : "=r"(a) : "l"(p));
    return a;
}

template<int OUTC, bool RELU>
__global__ __launch_bounds__(256, 2)
void sage_mma(const float* __restrict__ X, const float* __restrict__ AGG,
              const float* __restrict__ bias, float* __restrict__ Y,
              int N, int wOff) {
    extern __shared__ char smem[];
    constexpr int OFF_AH = 0;
    constexpr int OFF_AL = A_BYT;
    constexpr int OFF_BH = 2 * A_BYT;
    constexpr int B_BYT  = OUTC * ASTR * 2;
    constexpr int OFF_BL = OFF_BH + B_BYT;

    const int t = threadIdx.x;
    const int wid = t >> 5;
    const int lane = t & 31;
    const int node0 = blockIdx.x * 64;

    const int warp_m = wid >> 2;
    const int warp_n = wid & 3;
    constexpr int WN = OUTC / 4;
    constexpr int NB = WN / 8;

    const int tid4 = lane & 3;
    const int grp  = lane >> 2;
    const int arow_in = lane & 15;
    const int acol    = (lane >> 4) * 8;

    float acc[2][NB][4];
#pragma unroll
    for (int m = 0; m < 2; m++)
#pragma unroll
        for (int nb = 0; nb < NB; nb++)
#pragma unroll
            for (int j = 0; j < 4; j++) acc[m][nb][j] = 0.f;

    const uint32_t sbase = smem_u32(smem);

#pragma unroll 1
    for (int p = 0; p < 2; p++) {
        const float* SRC = (p == 0) ? AGG : X;

        // ---- Stage A for this phase: 64 rows x 128 k, split hi/lo ----
        for (int i = t; i < 64 * 32; i += 256) {
            int row = i >> 5;
            int k = (i & 31) * 4;
            int node = node0 + row;
            float4 v = make_float4(0.f, 0.f, 0.f, 0.f);
            if (node < N)
                v = ((const float4*)(SRC + (long long)node * HID))[k >> 2];
            __nv_bfloat16 h0, h1, h2, h3, l0, l1, l2, l3;
            split_bf(v.x, h0, l0); split_bf(v.y, h1, l1);
            split_bf(v.z, h2, l2); split_bf(v.w, h3, l3);
            __nv_bfloat162 hA(h0, h1), hB(h2, h3), lA(l0, l1), lB(l2, l3);
            uint2 hp, lp;
            memcpy(&hp.x, &hA, 4); memcpy(&hp.y, &hB, 4);
            memcpy(&lp.x, &lA, 4); memcpy(&lp.y, &lB, 4);
            uint32_t off = (uint32_t)(row * (ASTR * 2) + k * 2);
            *(uint2*)(smem + OFF_AH + off) = hp;
            *(uint2*)(smem + OFF_AL + off) = lp;
        }

        // ---- Stage B for this phase: OUTC rows x 128 k from prepped weights ----
        for (int i = t; i < OUTC * 16; i += 256) {
            int n = i >> 4;
            int c = i & 15;                       // 16B chunk (8 bf16)
            int gsrc = (wOff + n * 256 + p * 128) / 8 + c;
            uint32_t off = (uint32_t)(n * (ASTR * 2) + c * 16);
            *(uint4*)(smem + OFF_BH + off) = ((const uint4*)g_whi)[gsrc];
            *(uint4*)(smem + OFF_BL + off) = ((const uint4*)g_wlo)[gsrc];
        }
        __syncthreads();

        // ---- 3-term MMA over this phase's K=128 ----
#pragma unroll 1
        for (int term = 0; term < 3; term++) {
            const uint32_t Abase = sbase + ((term == 2) ? OFF_AL : OFF_AH);
            const uint32_t Bbase = sbase + ((term == 1) ? OFF_BL : OFF_BH);
            const uint32_t aAddr0 = Abase + (uint32_t)((warp_m * 32 + arow_in) * (ASTR * 2));
            const uint32_t bAddr0 = Bbase + (uint32_t)((warp_n * WN + grp) * (ASTR * 2));
#pragma unroll
            for (int k0 = 0; k0 < 128; k0 += 16) {
                uint32_t a[2][4];
#pragma unroll
                for (int m = 0; m < 2; m++)
                    ldmA(a[m], aAddr0 + (uint32_t)(m * 16 * (ASTR * 2) + (k0 + acol) * 2));
                uint32_t bf[NB][2];
#pragma unroll
                for (int nb = 0; nb < NB; nb++) {
                    uint32_t ba = bAddr0 + (uint32_t)(nb * 8 * (ASTR * 2) + (k0 + tid4 * 2) * 2);
                    asm volatile("ld.shared.b32 %0, [%1];" : "=r"(bf[nb][0]) : "r"(ba));
                    asm volatile("ld.shared.b32 %0, [%1];" : "=r"(bf[nb][1]) : "r"(ba + 16));
                }
#pragma unroll
                for (int m = 0; m < 2; m++)
#pragma unroll
                    for (int nb = 0; nb < NB; nb++)
                        mma16816(acc[m][nb], a[m], bf[nb]);
            }
        }
        __syncthreads();   // all warps done reading smem before next phase restages
    }

    // ---- Epilogue: bias + activation, direct global store ----
#pragma unroll
    for (int nb = 0; nb < NB; nb++) {
        const int col0 = warp_n * WN + nb * 8 + tid4 * 2;
        const float bx = __ldg(bias + col0);
        const float by = __ldg(bias + col0 + 1);
#pragma unroll
        for (int m = 0; m < 2; m++) {
            int r0 = node0 + warp_m * 32 + m * 16 + grp;
#pragma unroll
            for (int h = 0; h < 2; h++) {
                int node = r0 + h * 8;
                if (node < N) {
                    float2 o;
                    o.x = acc[m][nb][h * 2 + 0] + bx;
                    o.y = acc[m][nb][h * 2 + 1] + by;
                    if (RELU) { o.x = fmaxf(o.x, 0.f); o.y = fmaxf(o.y, 0.f); }
                    *(float2*)(Y + (long long)node * OUTC + col0) = o;
                }
            }
        }
    }
}

// ======================= Driver =======================

template<int OUTC, bool RELU>
static void run_layer(const float* X, const float* b, float* Y, int N,
                      float* p_agg, int wOff) {
    csr_aggregate<<<(N * 32 + 255) / 256, 256>>>(X, p_agg, N);
    size_t smem = 2 * A_BYT + 2 * (size_t)OUTC * ASTR * 2;
    sage_mma<OUTC, RELU><<<(N + 63) / 64, 256, smem>>>(X, p_agg, b, Y, N, wOff);
}

extern "C" void kernel_launch(void* const* d_in, const int* in_sizes, int n_in,
                              void* d_out, int out_size) {
    const float* x   = (const float*)d_in[0];
    const int*   ei  = (const int*)  d_in[1];
    const float* W1l = (const float*)d_in[2];
    const float* W1r = (const float*)d_in[3];
    const float* b1  = (const float*)d_in[4];
    const float* W2l = (const float*)d_in[5];
    const float* W2r = (const float*)d_in[6];
    const float* b2  = (const float*)d_in[7];
    const float* W3l = (const float*)d_in[8];
    const float* W3r = (const float*)d_in[9];
    const float* b3  = (const float*)d_in[10];
    float* out = (float*)d_out;

    const int N = in_sizes[0] / HID;   // 50000
    const int E = in_sizes[1] / 2;     // 500000
    const int* src = ei;
    const int* dst = ei + E;

    float *p_agg, *p_h1, *p_h2;
    int *p_cnt, *p_cur;
    cudaGetSymbolAddress((void**)&p_agg, g_agg);
    cudaGetSymbolAddress((void**)&p_h1,  g_h1);
    cudaGetSymbolAddress((void**)&p_h2,  g_h2);
    cudaGetSymbolAddress((void**)&p_cnt, g_cnt);
    cudaGetSymbolAddress((void**)&p_cur, g_cur);

    cudaFuncSetAttribute(sage_mma<128, true>,
                         cudaFuncAttributeMaxDynamicSharedMemorySize,
                         2 * A_BYT + 2 * 128 * ASTR * 2);
    cudaFuncSetAttribute(sage_mma<64, false>,
                         cudaFuncAttributeMaxDynamicSharedMemorySize,
                         2 * A_BYT + 2 * 64 * ASTR * 2);

    // Weight prep for all layers (independent of CSR build)
    prep_w_all<<<(81920 + 255) / 256, 256>>>(W1l, W1r, W2l, W2r, W3l, W3r);

    // CSR build with hierarchical coalesced scan
    const int NB_BLK = (N + 255) / 256;   // 196 <= 256
    zero_ints<<<(N + 255) / 256, 256>>>(p_cnt, p_cur, N);
    hist_kernel<<<(E + 255) / 256, 256>>>(dst, E);
    scan_blk<<<NB_BLK, 256>>>(N);
    scan_bsum<<<1, 256>>>(NB_BLK);
    scan_add<<<NB_BLK, 256>>>(N, E);
    fill_kernel<<<(E + 255) / 256, 256>>>(src, dst, E);

    run_layer<128, true >(x,    b1, p_h1, N, p_agg, 0);
    run_layer<128, true >(p_h1, b2, p_h2, N, p_agg, 32768);
    run_layer<64,  false>(p_h2, b3, out,  N, p_agg, 65536);
}